// round 1
// baseline (speedup 1.0000x reference)
#include <cuda_runtime.h>
#include <math.h>

// Problem constants
#define BB 512
#define SS 512
#define DD 300
#define PP 3

// ---------------- scratch (device globals, no allocation) ----------------
__device__ float g_x[BB * DD];     // hop state x
__device__ float g_xh[BB * DD];    // xh = x @ Wx.T + bx
__device__ float g_am[BB * DD];    // attn_mem = attn @ memory
__device__ float g_ks[BB * SS];    // k_score per token
__device__ int   g_lens[BB];
__device__ __align__(16) float g_v[DD];  // Wk.T @ wk_part
__device__ float g_u[DD];                // Wq.T @ wq_part
__device__ float g_ck;                   // bk . wk_part
__device__ float g_cq;                   // bq . wq_part
__device__ float g_Wc[DD * DD];          // Wp @ Wk
__device__ float g_bc[DD];               // bp + Wp @ bk

// ---------------- precompute collapsed vectors -----------------
__global__ void k_prep_vec(const float* __restrict__ Wk, const float* __restrict__ Wq,
                           const float* __restrict__ wmlp, const float* __restrict__ bk,
                           const float* __restrict__ bq) {
    int d = threadIdx.x;
    if (d < DD) {
        float sv = 0.f, su = 0.f;
        for (int e = 0; e < DD; e++) {
            sv += Wk[e * DD + d] * wmlp[e];
            su += Wq[e * DD + d] * wmlp[DD + e];
        }
        g_v[d] = sv;
        g_u[d] = su;
    }
    if (d == 0) {
        float ck = 0.f, cq = 0.f;
        for (int e = 0; e < DD; e++) {
            ck += bk[e] * wmlp[e];
            cq += bq[e] * wmlp[DD + e];
        }
        g_ck = ck;
        g_cq = cq;
    }
}

// Wc = Wp @ Wk, bc = bp + Wp @ bk.  4 p-rows per block.
__global__ void k_prep_Wc(const float* __restrict__ Wp, const float* __restrict__ Wk,
                          const float* __restrict__ bk, const float* __restrict__ bp) {
    int p0 = blockIdx.x * 4;
    int tid = threadIdx.x;
    __shared__ float srow[4 * DD];
    for (int i = tid; i < 4 * DD; i += blockDim.x) srow[i] = Wp[p0 * DD + i];
    __syncthreads();
    for (int d = tid; d < DD; d += blockDim.x) {
        float a0 = 0.f, a1 = 0.f, a2 = 0.f, a3 = 0.f;
        for (int e = 0; e < DD; e++) {
            float wk = Wk[e * DD + d];
            a0 += srow[0 * DD + e] * wk;
            a1 += srow[1 * DD + e] * wk;
            a2 += srow[2 * DD + e] * wk;
            a3 += srow[3 * DD + e] * wk;
        }
        g_Wc[(p0 + 0) * DD + d] = a0;
        g_Wc[(p0 + 1) * DD + d] = a1;
        g_Wc[(p0 + 2) * DD + d] = a2;
        g_Wc[(p0 + 3) * DD + d] = a3;
    }
    if (tid < 4) {
        float s = bp[p0 + tid];
        for (int e = 0; e < DD; e++) s += srow[tid * DD + e] * bk[e];
        g_bc[p0 + tid] = s;
    }
}

// ---------------- lens + aspect mean (initial x) -----------------
__global__ void k_lens_aspect(const int* __restrict__ text, const int* __restrict__ asp,
                              const float* __restrict__ emb) {
    int b = blockIdx.x, tid = threadIdx.x;
    __shared__ int s_asp[8];
    __shared__ int s_red[4];
    __shared__ float s_invn;
    if (tid < 8) s_asp[tid] = asp[b * 8 + tid];
    int cnt = 0;
    for (int s = tid; s < SS; s += 128) cnt += (text[b * SS + s] != 0);
#pragma unroll
    for (int o = 16; o; o >>= 1) cnt += __shfl_xor_sync(0xffffffffu, cnt, o);
    if ((tid & 31) == 0) s_red[tid >> 5] = cnt;
    __syncthreads();
    if (tid == 0) {
        g_lens[b] = s_red[0] + s_red[1] + s_red[2] + s_red[3];
        int na = 0;
        for (int a = 0; a < 8; a++) na += (s_asp[a] != 0);
        s_invn = 1.0f / (float)na;
    }
    __syncthreads();
    float invn = s_invn;
    for (int d = tid; d < DD; d += 128) {
        float ssum = 0.f;
#pragma unroll
        for (int a = 0; a < 8; a++) ssum += emb[(size_t)s_asp[a] * DD + d];  // emb[0]==0
        g_x[b * DD + d] = ssum * invn;
    }
}

// ---------------- k_score: one warp per token -----------------
__global__ void k_kscore(const int* __restrict__ text, const float* __restrict__ emb) {
    __shared__ float4 sv4[75];
    for (int i = threadIdx.x; i < 75; i += blockDim.x)
        sv4[i] = reinterpret_cast<const float4*>(g_v)[i];
    __syncthreads();
    int wid = (blockIdx.x * blockDim.x + threadIdx.x) >> 5;
    int lane = threadIdx.x & 31;
    if (wid >= BB * SS) return;
    int idx = text[wid];
    float out;
    if (idx == 0) {
        out = g_ck;  // memory row is zero -> k_score = bk.wk
    } else {
        const float4* row = reinterpret_cast<const float4*>(emb + (size_t)idx * DD);
        float acc = 0.f;
        for (int i = lane; i < 75; i += 32) {
            float4 e = row[i];
            float4 vv = sv4[i];
            acc += e.x * vv.x + e.y * vv.y + e.z * vv.z + e.w * vv.w;
        }
#pragma unroll
        for (int o = 16; o; o >>= 1) acc += __shfl_xor_sync(0xffffffffu, acc, o);
        int b = wid >> 9;
        int len = g_lens[b];
        int s = wid & (SS - 1);
        float w = 1.0f - (float)(s - (SS - len)) / (float)len;
        out = w * acc + g_ck;
    }
    if (lane == 0) g_ks[wid] = out;
}

// ---------------- small GEMM: out = Xin @ W.T + bias (+ residual) ----------
// MODE 0: g_xh = g_x @ Wx.T + bx
// MODE 1: g_x  = g_am @ g_Wc.T + g_bc + g_xh
template <int MODE>
__global__ void k_gemm(const float* __restrict__ Wext, const float* __restrict__ bext) {
    const float* __restrict__ Xin = MODE ? g_am : g_x;
    const float* __restrict__ Wm  = MODE ? g_Wc : Wext;
    const float* __restrict__ bi  = MODE ? g_bc : bext;
    int wg = (blockIdx.x * blockDim.x + threadIdx.x) >> 5;
    int lane = threadIdx.x & 31;
    if (wg >= 128 * 75) return;          // 512/4 row tiles x 300/4 col tiles
    int rt = wg / 75, ct = wg - rt * 75;
    int b0 = rt << 2, d0 = ct << 2;
    float acc[4][4] = {};
    for (int k = lane; k < DD; k += 32) {
        float xv[4], wv[4];
#pragma unroll
        for (int r = 0; r < 4; r++) xv[r] = Xin[(b0 + r) * DD + k];
#pragma unroll
        for (int c = 0; c < 4; c++) wv[c] = Wm[(d0 + c) * DD + k];
#pragma unroll
        for (int r = 0; r < 4; r++)
#pragma unroll
            for (int c = 0; c < 4; c++) acc[r][c] += xv[r] * wv[c];
    }
#pragma unroll
    for (int r = 0; r < 4; r++)
#pragma unroll
        for (int c = 0; c < 4; c++) {
            float a = acc[r][c];
#pragma unroll
            for (int o = 16; o; o >>= 1) a += __shfl_xor_sync(0xffffffffu, a, o);
            if (lane == (r * 4 + c)) {
                float val = a + bi[d0 + c];
                if (MODE) val += g_xh[(b0 + r) * DD + d0 + c];
                (MODE ? g_x : g_xh)[(b0 + r) * DD + d0 + c] = val;
            }
        }
}

// ---------------- per-hop attention + weighted gather -----------------
// One block per batch row. blockDim = 320.
__global__ void k_attn(const int* __restrict__ text, const float* __restrict__ emb) {
    const int NT = 320;
    int b = blockIdx.x, tid = threadIdx.x;
    __shared__ float s_coef[SS];
    __shared__ int   s_idx[SS];
    __shared__ float s_red[16];
    __shared__ float s_bcast;

    for (int s = tid; s < SS; s += NT) s_idx[s] = text[b * SS + s];

    // q scalar = xh[b] . u + cq
    float qp = 0.f;
    for (int d = tid; d < DD; d += NT) qp += g_xh[b * DD + d] * g_u[d];
#pragma unroll
    for (int o = 16; o; o >>= 1) qp += __shfl_xor_sync(0xffffffffu, qp, o);
    if ((tid & 31) == 0) s_red[tid >> 5] = qp;
    __syncthreads();
    if (tid == 0) {
        float q = 0.f;
        for (int w = 0; w < NT / 32; w++) q += s_red[w];
        s_bcast = q + g_cq;
    }
    __syncthreads();
    float q = s_bcast;

    int len = g_lens[b];
    int s0 = SS - len;
    float invlen = 1.0f / (float)len;

    // scores: tanh is bounded in (-1,1) -> exp without max-subtraction is safe
    float esum = 0.f;
    for (int s = tid; s < SS; s += NT) {
        float e = expf(tanhf(g_ks[b * SS + s] + q));
        s_coef[s] = e;
        esum += e;
    }
#pragma unroll
    for (int o = 16; o; o >>= 1) esum += __shfl_xor_sync(0xffffffffu, esum, o);
    __syncthreads();
    if ((tid & 31) == 0) s_red[tid >> 5] = esum;
    __syncthreads();
    if (tid == 0) {
        float t = 0.f;
        for (int w = 0; w < NT / 32; w++) t += s_red[w];
        s_bcast = 1.0f / t;
    }
    __syncthreads();
    float inv = s_bcast;

    // fold softmax normalization and positional weight w into coef
    for (int s = tid; s < SS; s += NT)
        if (s >= s0) s_coef[s] *= inv * (1.0f - (float)(s - s0) * invlen);
    __syncthreads();

    // attn_mem[b, d] = sum over real tokens of coef_s * emb[idx_s, d]
    if (tid < DD) {
        float a0 = 0.f, a1 = 0.f, a2 = 0.f, a3 = 0.f;
        int s = s0;
        for (; s + 4 <= SS; s += 4) {
            a0 += s_coef[s + 0] * emb[(size_t)s_idx[s + 0] * DD + tid];
            a1 += s_coef[s + 1] * emb[(size_t)s_idx[s + 1] * DD + tid];
            a2 += s_coef[s + 2] * emb[(size_t)s_idx[s + 2] * DD + tid];
            a3 += s_coef[s + 3] * emb[(size_t)s_idx[s + 3] * DD + tid];
        }
        for (; s < SS; s++) a0 += s_coef[s] * emb[(size_t)s_idx[s] * DD + tid];
        g_am[b * DD + tid] = (a0 + a1) + (a2 + a3);
    }
}

// ---------------- final projection: out = x @ Wd.T + bd  (512 x 3) ----------
__global__ void k_final(const float* __restrict__ Wd, const float* __restrict__ bd,
                        float* __restrict__ out) {
    int wid = (blockIdx.x * blockDim.x + threadIdx.x) >> 5;
    int lane = threadIdx.x & 31;
    if (wid >= BB) return;
    float a0 = 0.f, a1 = 0.f, a2 = 0.f;
    for (int k = lane; k < DD; k += 32) {
        float xv = g_x[wid * DD + k];
        a0 += xv * Wd[0 * DD + k];
        a1 += xv * Wd[1 * DD + k];
        a2 += xv * Wd[2 * DD + k];
    }
#pragma unroll
    for (int o = 16; o; o >>= 1) {
        a0 += __shfl_xor_sync(0xffffffffu, a0, o);
        a1 += __shfl_xor_sync(0xffffffffu, a1, o);
        a2 += __shfl_xor_sync(0xffffffffu, a2, o);
    }
    if (lane == 0) {
        out[wid * PP + 0] = a0 + bd[0];
        out[wid * PP + 1] = a1 + bd[1];
        out[wid * PP + 2] = a2 + bd[2];
    }
}

// ---------------- launch -----------------
extern "C" void kernel_launch(void* const* d_in, const int* in_sizes, int n_in,
                              void* d_out, int out_size) {
    const int*   text = (const int*)d_in[0];
    const int*   asp  = (const int*)d_in[1];
    const float* emb  = (const float*)d_in[2];
    const float* Wx   = (const float*)d_in[3];
    const float* bx   = (const float*)d_in[4];
    const float* Wk   = (const float*)d_in[5];
    const float* bk   = (const float*)d_in[6];
    const float* Wq   = (const float*)d_in[7];
    const float* bq   = (const float*)d_in[8];
    const float* wmlp = (const float*)d_in[9];
    const float* Wp   = (const float*)d_in[10];
    const float* bp   = (const float*)d_in[11];
    const float* Wd   = (const float*)d_in[12];
    const float* bd   = (const float*)d_in[13];
    float* out = (float*)d_out;

    k_prep_vec<<<1, 320>>>(Wk, Wq, wmlp, bk, bq);
    k_prep_Wc<<<75, 128>>>(Wp, Wk, bk, bp);
    k_lens_aspect<<<BB, 128>>>(text, asp, emb);
    k_kscore<<<(BB * SS) / 8, 256>>>(text, emb);
    for (int h = 0; h < 3; h++) {
        k_gemm<0><<<1200, 256>>>(Wx, bx);
        k_attn<<<BB, 320>>>(text, emb);
        k_gemm<1><<<1200, 256>>>(nullptr, nullptr);
    }
    k_final<<<64, 256>>>(Wd, bd, out);
}

// round 2
// speedup vs baseline: 1.4079x; 1.4079x over previous
#include <cuda_runtime.h>
#include <math.h>

#define BB 512
#define SS 512
#define VV 50000
#define DD 300
#define PP 3
#define D4 75   // DD/4

// ---------------- scratch (device globals) ----------------
__device__ __align__(16) float g_xA[BB * DD];
__device__ __align__(16) float g_xB[BB * DD];
__device__ __align__(16) float g_am[BB * DD];
__device__ float g_sv[VV];              // emb[i] . v  per vocab entry
__device__ int   g_lens[BB];
__device__ __align__(16) float g_v[DD]; // Wk^T wk
__device__ float g_u[DD];               // Wq^T wq
__device__ float g_u2[DD];              // Wx^T u
__device__ float g_ck;                  // bk . wk
__device__ float g_cq;                  // bq . wq
__device__ float g_c2;                  // bx . u + cq
__device__ float g_Wc[DD * DD];         // Wp @ Wk
__device__ float g_bc[DD];              // bp + Wp bk + bx  (fused bias)

// ---------------- prep 1: v, u, ck, cq -----------------
__global__ void k_prep1(const float* __restrict__ Wk, const float* __restrict__ Wq,
                        const float* __restrict__ wmlp, const float* __restrict__ bk,
                        const float* __restrict__ bq) {
    int d = threadIdx.x;
    if (d < DD) {
        float sv = 0.f, su = 0.f;
        for (int e = 0; e < DD; e++) {
            sv += Wk[e * DD + d] * wmlp[e];
            su += Wq[e * DD + d] * wmlp[DD + e];
        }
        g_v[d] = sv;
        g_u[d] = su;
    }
    if (d == 0) {
        float ck = 0.f, cq = 0.f;
        for (int e = 0; e < DD; e++) {
            ck += bk[e] * wmlp[e];
            cq += bq[e] * wmlp[DD + e];
        }
        g_ck = ck;
        g_cq = cq;
    }
}

// ---------------- prep 2: u2 = Wx^T u, c2 -----------------
__global__ void k_prep2(const float* __restrict__ Wx, const float* __restrict__ bx) {
    int d = threadIdx.x;
    if (d < DD) {
        float s = 0.f;
        for (int e = 0; e < DD; e++) s += Wx[e * DD + d] * g_u[e];
        g_u2[d] = s;
    }
    if (d == 0) {
        float c = g_cq;
        for (int e = 0; e < DD; e++) c += bx[e] * g_u[e];
        g_c2 = c;
    }
}

// ---------------- prep 3: Wc = Wp@Wk, bc = bp + Wp bk + bx ----------
__global__ void k_prep_Wc(const float* __restrict__ Wp, const float* __restrict__ Wk,
                          const float* __restrict__ bk, const float* __restrict__ bp,
                          const float* __restrict__ bx) {
    int p0 = blockIdx.x * 4;
    int tid = threadIdx.x;
    __shared__ float srow[4 * DD];
    for (int i = tid; i < 4 * DD; i += blockDim.x) srow[i] = Wp[p0 * DD + i];
    __syncthreads();
    for (int d = tid; d < DD; d += blockDim.x) {
        float a0 = 0.f, a1 = 0.f, a2 = 0.f, a3 = 0.f;
        for (int e = 0; e < DD; e++) {
            float wk = Wk[e * DD + d];
            a0 += srow[0 * DD + e] * wk;
            a1 += srow[1 * DD + e] * wk;
            a2 += srow[2 * DD + e] * wk;
            a3 += srow[3 * DD + e] * wk;
        }
        g_Wc[(p0 + 0) * DD + d] = a0;
        g_Wc[(p0 + 1) * DD + d] = a1;
        g_Wc[(p0 + 2) * DD + d] = a2;
        g_Wc[(p0 + 3) * DD + d] = a3;
    }
    if (tid < 4) {
        float s = bp[p0 + tid] + bx[p0 + tid];
        for (int e = 0; e < DD; e++) s += srow[tid * DD + e] * bk[e];
        g_bc[p0 + tid] = s;
    }
}

// ---------------- per-vocab score: sv[i] = emb[i] . v -----------------
// One warp per vocab row. 128 threads/block.
__global__ void k_vocab(const float* __restrict__ emb) {
    __shared__ float4 sv4[D4];
    for (int i = threadIdx.x; i < D4; i += blockDim.x)
        sv4[i] = reinterpret_cast<const float4*>(g_v)[i];
    __syncthreads();
    int row = blockIdx.x * 4 + (threadIdx.x >> 5);
    int lane = threadIdx.x & 31;
    if (row >= VV) return;
    const float4* er = reinterpret_cast<const float4*>(emb + (size_t)row * DD);
    float acc = 0.f;
#pragma unroll
    for (int i = lane; i < D4; i += 32) {
        float4 e = er[i];
        float4 vv = sv4[i];
        acc += e.x * vv.x + e.y * vv.y + e.z * vv.z + e.w * vv.w;
    }
#pragma unroll
    for (int o = 16; o; o >>= 1) acc += __shfl_xor_sync(0xffffffffu, acc, o);
    if (lane == 0) g_sv[row] = acc;
}

// ---------------- lens + aspect mean (initial x into g_xA) -----------------
__global__ void k_lens_aspect(const int* __restrict__ text, const int* __restrict__ asp,
                              const float* __restrict__ emb) {
    int b = blockIdx.x, tid = threadIdx.x;
    __shared__ int s_asp[8];
    __shared__ int s_red[4];
    __shared__ float s_invn;
    if (tid < 8) s_asp[tid] = asp[b * 8 + tid];
    int cnt = 0;
    for (int s = tid; s < SS; s += 128) cnt += (text[b * SS + s] != 0);
#pragma unroll
    for (int o = 16; o; o >>= 1) cnt += __shfl_xor_sync(0xffffffffu, cnt, o);
    if ((tid & 31) == 0) s_red[tid >> 5] = cnt;
    __syncthreads();
    if (tid == 0) {
        g_lens[b] = s_red[0] + s_red[1] + s_red[2] + s_red[3];
        int na = 0;
        for (int a = 0; a < 8; a++) na += (s_asp[a] != 0);
        s_invn = 1.0f / (float)na;
    }
    __syncthreads();
    float invn = s_invn;
    for (int d = tid; d < DD; d += 128) {
        float ssum = 0.f;
#pragma unroll
        for (int a = 0; a < 8; a++) ssum += emb[(size_t)s_asp[a] * DD + d];  // emb[0]==0
        g_xA[b * DD + d] = ssum * invn;
    }
}

// ---------------- per-hop: q + softmax + weighted gather -----------------
// One block per batch row, 384 threads. XIN: 0 -> g_xA, 1 -> g_xB.
template <int XIN>
__global__ void k_attn(const int* __restrict__ text, const float* __restrict__ emb) {
    const int NT = 384;
    const float* __restrict__ Xin = XIN ? g_xB : g_xA;
    int b = blockIdx.x, tid = threadIdx.x;
    __shared__ float s_coef[SS];
    __shared__ int   s_idx[SS];
    __shared__ float4 s_part[4][D4];
    __shared__ float s_red[12];
    __shared__ float s_bcast;

    for (int s = tid; s < SS; s += NT) s_idx[s] = text[b * SS + s];

    // q = x_b . u2 + c2
    float qp = 0.f;
    for (int d = tid; d < DD; d += NT) qp += Xin[b * DD + d] * g_u2[d];
#pragma unroll
    for (int o = 16; o; o >>= 1) qp += __shfl_xor_sync(0xffffffffu, qp, o);
    if ((tid & 31) == 0) s_red[tid >> 5] = qp;
    __syncthreads();
    if (tid == 0) {
        float q = 0.f;
        for (int w = 0; w < 12; w++) q += s_red[w];
        s_bcast = q + g_c2;
    }
    __syncthreads();
    float q = s_bcast;

    int len = g_lens[b];
    int s0 = SS - len;
    float invlen = 1.0f / (float)len;
    float ckq = g_ck + q;

    // scores over real tokens only; tanh bounded -> no max subtraction needed
    float esum = 0.f;
    for (int s = s0 + tid; s < SS; s += NT) {
        float w = 1.0f - (float)(s - s0) * invlen;
        float e = expf(tanhf(w * g_sv[s_idx[s]] + ckq));
        s_coef[s] = e;
        esum += e;
    }
#pragma unroll
    for (int o = 16; o; o >>= 1) esum += __shfl_xor_sync(0xffffffffu, esum, o);
    if ((tid & 31) == 0) s_red[tid >> 5] = esum;
    __syncthreads();
    if (tid == 0) {
        float t = (float)s0 * expf(tanhf(ckq));  // padding tokens' softmax mass
        for (int w = 0; w < 12; w++) t += s_red[w];
        s_bcast = 1.0f / t;
    }
    __syncthreads();
    float inv = s_bcast;

    // fold softmax norm + positional weight into coef (pad rows never gathered)
    for (int s = s0 + tid; s < SS; s += NT) {
        float w = 1.0f - (float)(s - s0) * invlen;
        s_coef[s] *= inv * w;
    }
    __syncthreads();

    // gather: 4 token-groups x 75 float4 chunks
    if (tid < 300) {
        int grp = tid / D4;
        int ch = tid - grp * D4;
        const float4* eb = reinterpret_cast<const float4*>(emb);
        float4 acc = make_float4(0.f, 0.f, 0.f, 0.f);
#pragma unroll 2
        for (int s = s0 + grp; s < SS; s += 4) {
            float c = s_coef[s];
            float4 e = eb[(size_t)s_idx[s] * D4 + ch];
            acc.x += c * e.x; acc.y += c * e.y; acc.z += c * e.z; acc.w += c * e.w;
        }
        s_part[grp][ch] = acc;
    }
    __syncthreads();
    if (tid < D4) {
        float4 a0 = s_part[0][tid], a1 = s_part[1][tid];
        float4 a2 = s_part[2][tid], a3 = s_part[3][tid];
        float4 r;
        r.x = (a0.x + a1.x) + (a2.x + a3.x);
        r.y = (a0.y + a1.y) + (a2.y + a3.y);
        r.z = (a0.z + a1.z) + (a2.z + a3.z);
        r.w = (a0.w + a1.w) + (a2.w + a3.w);
        reinterpret_cast<float4*>(g_am)[b * D4 + tid] = r;
    }
}

// ---------------- fused hop GEMM: x_out = am@Wc^T + x_in@Wx^T + bc ----------
// Warp computes a 4x4 output tile; K = 600 (two 300 segments).
template <int XIN>
__global__ void k_gemm(const float* __restrict__ Wx) {
    const float* __restrict__ Xin  = XIN ? g_xB : g_xA;
    float* __restrict__       Xout = XIN ? g_xA : g_xB;
    int wg = (blockIdx.x * blockDim.x + threadIdx.x) >> 5;
    int lane = threadIdx.x & 31;
    if (wg >= 128 * D4) return;
    int rt = wg / D4, ct = wg - rt * D4;
    int b0 = rt << 2, d0 = ct << 2;
    float acc[4][4] = {};
#pragma unroll 1
    for (int k = lane; k < DD; k += 32) {
        float xv[4], wv[4];
#pragma unroll
        for (int r = 0; r < 4; r++) xv[r] = g_am[(b0 + r) * DD + k];
#pragma unroll
        for (int c = 0; c < 4; c++) wv[c] = g_Wc[(d0 + c) * DD + k];
#pragma unroll
        for (int r = 0; r < 4; r++)
#pragma unroll
            for (int c = 0; c < 4; c++) acc[r][c] += xv[r] * wv[c];
    }
#pragma unroll 1
    for (int k = lane; k < DD; k += 32) {
        float xv[4], wv[4];
#pragma unroll
        for (int r = 0; r < 4; r++) xv[r] = Xin[(b0 + r) * DD + k];
#pragma unroll
        for (int c = 0; c < 4; c++) wv[c] = Wx[(d0 + c) * DD + k];
#pragma unroll
        for (int r = 0; r < 4; r++)
#pragma unroll
            for (int c = 0; c < 4; c++) acc[r][c] += xv[r] * wv[c];
    }
#pragma unroll
    for (int r = 0; r < 4; r++)
#pragma unroll
        for (int c = 0; c < 4; c++) {
            float a = acc[r][c];
#pragma unroll
            for (int o = 16; o; o >>= 1) a += __shfl_xor_sync(0xffffffffu, a, o);
            if (lane == (r * 4 + c))
                Xout[(b0 + r) * DD + d0 + c] = a + g_bc[d0 + c];
        }
}

// ---------------- final projection: out = x @ Wd.T + bd ----------
template <int XBUF>
__global__ void k_final(const float* __restrict__ Wd, const float* __restrict__ bd,
                        float* __restrict__ out) {
    const float* __restrict__ X = XBUF ? g_xB : g_xA;
    int wid = (blockIdx.x * blockDim.x + threadIdx.x) >> 5;
    int lane = threadIdx.x & 31;
    if (wid >= BB) return;
    float a0 = 0.f, a1 = 0.f, a2 = 0.f;
    for (int k = lane; k < DD; k += 32) {
        float xv = X[wid * DD + k];
        a0 += xv * Wd[0 * DD + k];
        a1 += xv * Wd[1 * DD + k];
        a2 += xv * Wd[2 * DD + k];
    }
#pragma unroll
    for (int o = 16; o; o >>= 1) {
        a0 += __shfl_xor_sync(0xffffffffu, a0, o);
        a1 += __shfl_xor_sync(0xffffffffu, a1, o);
        a2 += __shfl_xor_sync(0xffffffffu, a2, o);
    }
    if (lane == 0) {
        out[wid * PP + 0] = a0 + bd[0];
        out[wid * PP + 1] = a1 + bd[1];
        out[wid * PP + 2] = a2 + bd[2];
    }
}

// ---------------- launch -----------------
extern "C" void kernel_launch(void* const* d_in, const int* in_sizes, int n_in,
                              void* d_out, int out_size) {
    const int*   text = (const int*)d_in[0];
    const int*   asp  = (const int*)d_in[1];
    const float* emb  = (const float*)d_in[2];
    const float* Wx   = (const float*)d_in[3];
    const float* bx   = (const float*)d_in[4];
    const float* Wk   = (const float*)d_in[5];
    const float* bk   = (const float*)d_in[6];
    const float* Wq   = (const float*)d_in[7];
    const float* bq   = (const float*)d_in[8];
    const float* wmlp = (const float*)d_in[9];
    const float* Wp   = (const float*)d_in[10];
    const float* bp   = (const float*)d_in[11];
    const float* Wd   = (const float*)d_in[12];
    const float* bd   = (const float*)d_in[13];
    float* out = (float*)d_out;

    k_prep1<<<1, 320>>>(Wk, Wq, wmlp, bk, bq);
    k_prep2<<<1, 320>>>(Wx, bx);
    k_prep_Wc<<<75, 128>>>(Wp, Wk, bk, bp, bx);
    k_vocab<<<(VV + 3) / 4, 128>>>(emb);
    k_lens_aspect<<<BB, 128>>>(text, asp, emb);

    // hop 0: x in A -> x' in B ; hop 1: B -> A ; hop 2: A -> B
    k_attn<0><<<BB, 384>>>(text, emb);
    k_gemm<0><<<1200, 256>>>(Wx);
    k_attn<1><<<BB, 384>>>(text, emb);
    k_gemm<1><<<1200, 256>>>(Wx);
    k_attn<0><<<BB, 384>>>(text, emb);
    k_gemm<0><<<1200, 256>>>(Wx);

    k_final<1><<<64, 256>>>(Wd, bd, out);
}

// round 3
// speedup vs baseline: 1.6512x; 1.1729x over previous
#include <cuda_runtime.h>
#include <cuda_fp16.h>
#include <math.h>

#define BB 512
#define SS 512
#define VV 50000
#define DD 300
#define PP 3
#define D4 75     // DD/4
#define KK 640    // padded concat K: [am 0..299 |pad| x 320..619 |pad]
#define NN 320    // padded output dim
#define XOFF 320  // x-region offset inside concat row

// ---------------- scratch (device globals; statically zero-initialized) ------
__device__ __align__(16) float g_xcA[BB * KK];   // [am | x] buffer A
__device__ __align__(16) float g_xcB[BB * KK];   // [am | x] buffer B
__device__ __align__(16) float g_part[3][BB * NN]; // splitK partials
__device__ __align__(16) uint2 g_embh[(size_t)VV * D4]; // fp16 emb shadow (4 halves/chunk)
__device__ float g_sv[VV];               // emb[i] . v
__device__ int   g_lens[BB];
__device__ __align__(16) float g_v[DD];  // Wk^T wk
__device__ float g_u[DD];                // Wq^T wq
__device__ float g_u2[DD];               // Wx^T u
__device__ float g_ck, g_cq, g_c2;
__device__ __align__(16) float g_Wcat[NN * KK];  // rows 0..299: [Wc | pad | Wx | pad]; rows 300+ zero
__device__ __align__(16) float g_bc[NN];         // bp + Wp bk + bx (pad zero)

// ---------------- prep1: v, u, ck, cq (one warp per d) -----------------
__global__ void k_prep1(const float* __restrict__ Wk, const float* __restrict__ Wq,
                        const float* __restrict__ wmlp, const float* __restrict__ bk,
                        const float* __restrict__ bq) {
    int w = (blockIdx.x * blockDim.x + threadIdx.x) >> 5;
    int lane = threadIdx.x & 31;
    if (w < DD) {
        float sv = 0.f, su = 0.f;
        for (int e = lane; e < DD; e += 32) {
            sv += Wk[e * DD + w] * wmlp[e];
            su += Wq[e * DD + w] * wmlp[DD + e];
        }
#pragma unroll
        for (int o = 16; o; o >>= 1) {
            sv += __shfl_xor_sync(0xffffffffu, sv, o);
            su += __shfl_xor_sync(0xffffffffu, su, o);
        }
        if (lane == 0) { g_v[w] = sv; g_u[w] = su; }
    } else if (w == DD) {
        float ck = 0.f, cq = 0.f;
        for (int e = lane; e < DD; e += 32) {
            ck += bk[e] * wmlp[e];
            cq += bq[e] * wmlp[DD + e];
        }
#pragma unroll
        for (int o = 16; o; o >>= 1) {
            ck += __shfl_xor_sync(0xffffffffu, ck, o);
            cq += __shfl_xor_sync(0xffffffffu, cq, o);
        }
        if (lane == 0) { g_ck = ck; g_cq = cq; }
    }
}

// ---------------- prep2: u2 = Wx^T u, c2 (one warp per d) -----------------
__global__ void k_prep2(const float* __restrict__ Wx, const float* __restrict__ bx) {
    int w = (blockIdx.x * blockDim.x + threadIdx.x) >> 5;
    int lane = threadIdx.x & 31;
    if (w < DD) {
        float s = 0.f;
        for (int e = lane; e < DD; e += 32) s += Wx[e * DD + w] * g_u[e];
#pragma unroll
        for (int o = 16; o; o >>= 1) s += __shfl_xor_sync(0xffffffffu, s, o);
        if (lane == 0) g_u2[w] = s;
    } else if (w == DD) {
        float c = 0.f;
        for (int e = lane; e < DD; e += 32) c += bx[e] * g_u[e];
#pragma unroll
        for (int o = 16; o; o >>= 1) c += __shfl_xor_sync(0xffffffffu, c, o);
        if (lane == 0) g_c2 = c + g_cq;
    }
}

// ---------------- prep_W: build Wcat rows (Wc = Wp@Wk, copy Wx), bc ----------
__global__ void k_prep_W(const float* __restrict__ Wp, const float* __restrict__ Wk,
                         const float* __restrict__ bk, const float* __restrict__ bp,
                         const float* __restrict__ bx, const float* __restrict__ Wx) {
    int p0 = blockIdx.x * 4;
    int tid = threadIdx.x;
    __shared__ float srow[4 * DD];
    for (int i = tid; i < 4 * DD; i += blockDim.x) srow[i] = Wp[p0 * DD + i];
    __syncthreads();
    for (int d = tid; d < DD; d += blockDim.x) {
        float a0 = 0.f, a1 = 0.f, a2 = 0.f, a3 = 0.f;
        for (int e = 0; e < DD; e++) {
            float wk = Wk[e * DD + d];
            a0 += srow[0 * DD + e] * wk;
            a1 += srow[1 * DD + e] * wk;
            a2 += srow[2 * DD + e] * wk;
            a3 += srow[3 * DD + e] * wk;
        }
        g_Wcat[(p0 + 0) * KK + d] = a0;
        g_Wcat[(p0 + 1) * KK + d] = a1;
        g_Wcat[(p0 + 2) * KK + d] = a2;
        g_Wcat[(p0 + 3) * KK + d] = a3;
    }
    // copy Wx rows into concat cols [XOFF, XOFF+300)
    for (int i = tid; i < 4 * DD; i += blockDim.x) {
        int r = i / DD, c = i - r * DD;
        g_Wcat[(p0 + r) * KK + XOFF + c] = Wx[(p0 + r) * DD + c];
    }
    if (tid < 4) {
        float s = bp[p0 + tid] + bx[p0 + tid];
        for (int e = 0; e < DD; e++) s += srow[tid * DD + e] * bk[e];
        g_bc[p0 + tid] = s;
    }
}

// ---------------- vocab: sv[i] = emb[i].v  +  fp16 shadow -----------------
__global__ void k_vocab(const float* __restrict__ emb) {
    __shared__ float4 sv4[D4];
    for (int i = threadIdx.x; i < D4; i += blockDim.x)
        sv4[i] = reinterpret_cast<const float4*>(g_v)[i];
    __syncthreads();
    int row = blockIdx.x * 4 + (threadIdx.x >> 5);
    int lane = threadIdx.x & 31;
    if (row >= VV) return;
    const float4* er = reinterpret_cast<const float4*>(emb + (size_t)row * DD);
    float acc = 0.f;
#pragma unroll
    for (int i = lane; i < D4; i += 32) {
        float4 e = er[i];
        float4 vv = sv4[i];
        acc += e.x * vv.x + e.y * vv.y + e.z * vv.z + e.w * vv.w;
        __half2 h0 = __floats2half2_rn(e.x, e.y);
        __half2 h1 = __floats2half2_rn(e.z, e.w);
        uint2 u;
        u.x = *reinterpret_cast<unsigned*>(&h0);
        u.y = *reinterpret_cast<unsigned*>(&h1);
        g_embh[(size_t)row * D4 + i] = u;
    }
#pragma unroll
    for (int o = 16; o; o >>= 1) acc += __shfl_xor_sync(0xffffffffu, acc, o);
    if (lane == 0) g_sv[row] = acc;
}

// ---------------- lens + aspect mean (x into buffer A) -----------------
__global__ void k_lens_aspect(const int* __restrict__ text, const int* __restrict__ asp,
                              const float* __restrict__ emb) {
    int b = blockIdx.x, tid = threadIdx.x;
    __shared__ int s_asp[8];
    __shared__ int s_red[4];
    __shared__ float s_invn;
    if (tid < 8) s_asp[tid] = asp[b * 8 + tid];
    int cnt = 0;
    for (int s = tid; s < SS; s += 128) cnt += (text[b * SS + s] != 0);
#pragma unroll
    for (int o = 16; o; o >>= 1) cnt += __shfl_xor_sync(0xffffffffu, cnt, o);
    if ((tid & 31) == 0) s_red[tid >> 5] = cnt;
    __syncthreads();
    if (tid == 0) {
        g_lens[b] = s_red[0] + s_red[1] + s_red[2] + s_red[3];
        int na = 0;
        for (int a = 0; a < 8; a++) na += (s_asp[a] != 0);
        s_invn = 1.0f / (float)na;
    }
    __syncthreads();
    float invn = s_invn;
    for (int d = tid; d < DD; d += 128) {
        float ssum = 0.f;
#pragma unroll
        for (int a = 0; a < 8; a++) ssum += emb[(size_t)s_asp[a] * DD + d];  // emb[0]==0
        g_xcA[b * KK + XOFF + d] = ssum * invn;
    }
}

// ---------------- per-hop: q + softmax + fp16 weighted gather --------------
template <int CUR>
__global__ void k_attn(const int* __restrict__ text) {
    const int NT = 384;
    float* __restrict__ xc = CUR ? g_xcB : g_xcA;
    int b = blockIdx.x, tid = threadIdx.x;
    __shared__ float s_coef[SS];
    __shared__ int   s_idx[SS];
    __shared__ float4 s_part[4][D4];
    __shared__ float s_red[12];
    __shared__ float s_bcast;

    for (int s = tid; s < SS; s += NT) s_idx[s] = text[b * SS + s];

    // q = x_b . u2 + c2
    float qp = 0.f;
    for (int d = tid; d < DD; d += NT) qp += xc[b * KK + XOFF + d] * g_u2[d];
#pragma unroll
    for (int o = 16; o; o >>= 1) qp += __shfl_xor_sync(0xffffffffu, qp, o);
    if ((tid & 31) == 0) s_red[tid >> 5] = qp;
    __syncthreads();
    if (tid == 0) {
        float q = 0.f;
        for (int w = 0; w < 12; w++) q += s_red[w];
        s_bcast = q + g_c2;
    }
    __syncthreads();
    float q = s_bcast;

    int len = g_lens[b];
    int s0 = SS - len;
    float invlen = 1.0f / (float)len;
    float ckq = g_ck + q;

    float esum = 0.f;
    for (int s = s0 + tid; s < SS; s += NT) {
        float w = 1.0f - (float)(s - s0) * invlen;
        float e = expf(tanhf(w * g_sv[s_idx[s]] + ckq));
        s_coef[s] = e;
        esum += e;
    }
#pragma unroll
    for (int o = 16; o; o >>= 1) esum += __shfl_xor_sync(0xffffffffu, esum, o);
    if ((tid & 31) == 0) s_red[tid >> 5] = esum;
    __syncthreads();
    if (tid == 0) {
        float t = (float)s0 * expf(tanhf(ckq));  // padding softmax mass
        for (int w = 0; w < 12; w++) t += s_red[w];
        s_bcast = 1.0f / t;
    }
    __syncthreads();
    float inv = s_bcast;

    for (int s = s0 + tid; s < SS; s += NT) {
        float w = 1.0f - (float)(s - s0) * invlen;
        s_coef[s] *= inv * w;
    }
    __syncthreads();

    // gather (fp16, 8-deep MLP): 4 token-groups x 75 chunks of 4 floats
    if (tid < 300) {
        int grp = tid / D4;
        int ch = tid - grp * D4;
        float4 acc = make_float4(0.f, 0.f, 0.f, 0.f);
        int s = s0 + grp;
        for (; s + 28 < SS; s += 32) {
            int ix[8]; float cf[8];
#pragma unroll
            for (int j = 0; j < 8; j++) { ix[j] = s_idx[s + 4 * j]; cf[j] = s_coef[s + 4 * j]; }
            uint2 v[8];
#pragma unroll
            for (int j = 0; j < 8; j++) v[j] = g_embh[(size_t)ix[j] * D4 + ch];
#pragma unroll
            for (int j = 0; j < 8; j++) {
                float2 lo = __half22float2(*reinterpret_cast<__half2*>(&v[j].x));
                float2 hi = __half22float2(*reinterpret_cast<__half2*>(&v[j].y));
                acc.x += cf[j] * lo.x; acc.y += cf[j] * lo.y;
                acc.z += cf[j] * hi.x; acc.w += cf[j] * hi.y;
            }
        }
        for (; s < SS; s += 4) {
            float c = s_coef[s];
            uint2 v = g_embh[(size_t)s_idx[s] * D4 + ch];
            float2 lo = __half22float2(*reinterpret_cast<__half2*>(&v.x));
            float2 hi = __half22float2(*reinterpret_cast<__half2*>(&v.y));
            acc.x += c * lo.x; acc.y += c * lo.y;
            acc.z += c * hi.x; acc.w += c * hi.y;
        }
        s_part[grp][ch] = acc;
    }
    __syncthreads();
    if (tid < D4) {
        float4 a0 = s_part[0][tid], a1 = s_part[1][tid];
        float4 a2 = s_part[2][tid], a3 = s_part[3][tid];
        float4 r;
        r.x = (a0.x + a1.x) + (a2.x + a3.x);
        r.y = (a0.y + a1.y) + (a2.y + a3.y);
        r.z = (a0.z + a1.z) + (a2.z + a3.z);
        r.w = (a0.w + a1.w) + (a2.w + a3.w);
        reinterpret_cast<float4*>(xc + b * KK)[tid] = r;   // am region
    }
}

// ---------------- tiled GEMM: part[s] = Xcur[:, ks:ke] @ Wcat[:, ks:ke]^T ----
// BM=64 BN=64 BK=16, 256 threads, 4x4 thread tiles, double-buffered smem.
#define SROW 68
__device__ const int c_ks[4] = {0, 224, 448, 640};

template <int CUR>
__global__ __launch_bounds__(256, 2) void k_gemm() {
    const float* __restrict__ xc = CUR ? g_xcB : g_xcA;
    __shared__ float Xs[2][16 * SROW];
    __shared__ float Ws[2][16 * SROW];
    int tm = blockIdx.x, tn = blockIdx.y, sk = blockIdx.z;
    int b0 = tm * 64, d0 = tn * 64;
    int k0 = c_ks[sk], k1 = c_ks[sk + 1];
    int nt = (k1 - k0) >> 4;
    int tid = threadIdx.x;
    int lr = tid >> 2, lk = (tid & 3) << 2;          // load mapping
    int rt = tid >> 4, ct = tid & 15;                 // compute mapping

    float acc[4][4] = {};
    float4 rx, rw;

    // load tile 0
    rx = *reinterpret_cast<const float4*>(xc + (b0 + lr) * KK + k0 + lk);
    rw = *reinterpret_cast<const float4*>(g_Wcat + (d0 + lr) * KK + k0 + lk);
    {
        float* xs = Xs[0]; float* ws = Ws[0];
        xs[(lk + 0) * SROW + lr] = rx.x; xs[(lk + 1) * SROW + lr] = rx.y;
        xs[(lk + 2) * SROW + lr] = rx.z; xs[(lk + 3) * SROW + lr] = rx.w;
        ws[(lk + 0) * SROW + lr] = rw.x; ws[(lk + 1) * SROW + lr] = rw.y;
        ws[(lk + 2) * SROW + lr] = rw.z; ws[(lk + 3) * SROW + lr] = rw.w;
    }
    __syncthreads();

    for (int t = 0; t < nt; t++) {
        if (t + 1 < nt) {
            int kt = k0 + ((t + 1) << 4);
            rx = *reinterpret_cast<const float4*>(xc + (b0 + lr) * KK + kt + lk);
            rw = *reinterpret_cast<const float4*>(g_Wcat + (d0 + lr) * KK + kt + lk);
        }
        const float* xs = Xs[t & 1];
        const float* ws = Ws[t & 1];
#pragma unroll
        for (int kk = 0; kk < 16; kk++) {
            float4 xv = *reinterpret_cast<const float4*>(xs + kk * SROW + rt * 4);
            float4 wv = *reinterpret_cast<const float4*>(ws + kk * SROW + ct * 4);
            acc[0][0] += xv.x * wv.x; acc[0][1] += xv.x * wv.y; acc[0][2] += xv.x * wv.z; acc[0][3] += xv.x * wv.w;
            acc[1][0] += xv.y * wv.x; acc[1][1] += xv.y * wv.y; acc[1][2] += xv.y * wv.z; acc[1][3] += xv.y * wv.w;
            acc[2][0] += xv.z * wv.x; acc[2][1] += xv.z * wv.y; acc[2][2] += xv.z * wv.z; acc[2][3] += xv.z * wv.w;
            acc[3][0] += xv.w * wv.x; acc[3][1] += xv.w * wv.y; acc[3][2] += xv.w * wv.z; acc[3][3] += xv.w * wv.w;
        }
        __syncthreads();
        if (t + 1 < nt) {
            float* xs2 = Xs[(t + 1) & 1]; float* ws2 = Ws[(t + 1) & 1];
            xs2[(lk + 0) * SROW + lr] = rx.x; xs2[(lk + 1) * SROW + lr] = rx.y;
            xs2[(lk + 2) * SROW + lr] = rx.z; xs2[(lk + 3) * SROW + lr] = rx.w;
            ws2[(lk + 0) * SROW + lr] = rw.x; ws2[(lk + 1) * SROW + lr] = rw.y;
            ws2[(lk + 2) * SROW + lr] = rw.z; ws2[(lk + 3) * SROW + lr] = rw.w;
            __syncthreads();
        }
    }

    float* po = g_part[sk];
#pragma unroll
    for (int r = 0; r < 4; r++) {
        float4 o = make_float4(acc[r][0], acc[r][1], acc[r][2], acc[r][3]);
        *reinterpret_cast<float4*>(po + (b0 + rt * 4 + r) * NN + d0 + ct * 4) = o;
    }
}

// ---------------- reduce partials + bias -> next x -----------------
template <int NXT>
__global__ void k_reduce() {
    float* __restrict__ xn = NXT ? g_xcB : g_xcA;
    int idx = blockIdx.x * blockDim.x + threadIdx.x;   // 0 .. 512*80-1 (float4)
    int b = idx / 80, d4 = idx - b * 80;
    const float4* p0 = reinterpret_cast<const float4*>(g_part[0]);
    const float4* p1 = reinterpret_cast<const float4*>(g_part[1]);
    const float4* p2 = reinterpret_cast<const float4*>(g_part[2]);
    float4 a = p0[b * 80 + d4], c = p1[b * 80 + d4], e = p2[b * 80 + d4];
    float4 bias = reinterpret_cast<const float4*>(g_bc)[d4];
    float4 r;
    r.x = a.x + c.x + e.x + bias.x;
    r.y = a.y + c.y + e.y + bias.y;
    r.z = a.z + c.z + e.z + bias.z;
    r.w = a.w + c.w + e.w + bias.w;
    reinterpret_cast<float4*>(xn + b * KK + XOFF)[d4] = r;
}

// ---------------- final: out = x @ Wd.T + bd ----------
template <int XBUF>
__global__ void k_final(const float* __restrict__ Wd, const float* __restrict__ bd,
                        float* __restrict__ out) {
    const float* __restrict__ xc = XBUF ? g_xcB : g_xcA;
    int wid = (blockIdx.x * blockDim.x + threadIdx.x) >> 5;
    int lane = threadIdx.x & 31;
    if (wid >= BB) return;
    float a0 = 0.f, a1 = 0.f, a2 = 0.f;
    for (int k = lane; k < DD; k += 32) {
        float xv = xc[wid * KK + XOFF + k];
        a0 += xv * Wd[0 * DD + k];
        a1 += xv * Wd[1 * DD + k];
        a2 += xv * Wd[2 * DD + k];
    }
#pragma unroll
    for (int o = 16; o; o >>= 1) {
        a0 += __shfl_xor_sync(0xffffffffu, a0, o);
        a1 += __shfl_xor_sync(0xffffffffu, a1, o);
        a2 += __shfl_xor_sync(0xffffffffu, a2, o);
    }
    if (lane == 0) {
        out[wid * PP + 0] = a0 + bd[0];
        out[wid * PP + 1] = a1 + bd[1];
        out[wid * PP + 2] = a2 + bd[2];
    }
}

// ---------------- launch -----------------
extern "C" void kernel_launch(void* const* d_in, const int* in_sizes, int n_in,
                              void* d_out, int out_size) {
    const int*   text = (const int*)d_in[0];
    const int*   asp  = (const int*)d_in[1];
    const float* emb  = (const float*)d_in[2];
    const float* Wx   = (const float*)d_in[3];
    const float* bx   = (const float*)d_in[4];
    const float* Wk   = (const float*)d_in[5];
    const float* bk   = (const float*)d_in[6];
    const float* Wq   = (const float*)d_in[7];
    const float* bq   = (const float*)d_in[8];
    const float* wmlp = (const float*)d_in[9];
    const float* Wp   = (const float*)d_in[10];
    const float* bp   = (const float*)d_in[11];
    const float* Wd   = (const float*)d_in[12];
    const float* bd   = (const float*)d_in[13];
    float* out = (float*)d_out;

    dm3:;
    k_prep1<<<38, 256>>>(Wk, Wq, wmlp, bk, bq);
    k_prep2<<<38, 256>>>(Wx, bx);
    k_prep_W<<<75, 128>>>(Wp, Wk, bk, bp, bx, Wx);
    k_vocab<<<(VV + 3) / 4, 128>>>(emb);
    k_lens_aspect<<<BB, 128>>>(text, asp, emb);

    dim3 gg(8, 5, 3);
    // hop 0: A -> B
    k_attn<0><<<BB, 384>>>(text);
    k_gemm<0><<<gg, 256>>>();
    k_reduce<1><<<160, 256>>>();
    // hop 1: B -> A
    k_attn<1><<<BB, 384>>>(text);
    k_gemm<1><<<gg, 256>>>();
    k_reduce<0><<<160, 256>>>();
    // hop 2: A -> B
    k_attn<0><<<BB, 384>>>(text);
    k_gemm<0><<<gg, 256>>>();
    k_reduce<1><<<160, 256>>>();

    k_final<1><<<64, 256>>>(Wd, bd, out);
}